// round 1
// baseline (speedup 1.0000x reference)
#include <cuda_runtime.h>
#include <math.h>

#define NROWS_MAX 1000000
#define KEXP 8
#define TPB 256

typedef unsigned long long ull;

// ---------------- scratch (static device globals; no allocs allowed) --------
__device__ int g_counts[KEXP];
__device__ int g_off[KEXP + 1];
__device__ int g_cursor[KEXP];
__device__ int g_perm[NROWS_MAX];

// ---------------- packed-f32x2 helpers --------------------------------------
__device__ __forceinline__ ull fma2(ull a, ull b, ull c) {
    ull d;
    asm("fma.rn.f32x2 %0, %1, %2, %3;" : "=l"(d) : "l"(a), "l"(b), "l"(c));
    return d;
}
__device__ __forceinline__ ull dup2(float v) {
    ull d;
    asm("mov.b64 %0, {%1, %1};" : "=l"(d) : "f"(v));
    return d;
}
__device__ __forceinline__ ull pk2(float lo, float hi) {
    ull d;
    asm("mov.b64 %0, {%1, %2};" : "=l"(d) : "f"(lo), "f"(hi));
    return d;
}
__device__ __forceinline__ float2 up2(ull v) {
    float lo, hi;
    asm("mov.b64 {%0, %1}, %2;" : "=f"(lo), "=f"(hi) : "l"(v));
    return make_float2(lo, hi);
}

// ---------------- bucketing kernels ------------------------------------------
__global__ void k_zero() {
    if (threadIdx.x < KEXP) g_counts[threadIdx.x] = 0;
}

__global__ void k_hist(const int* __restrict__ y, int n) {
    __shared__ int s[KEXP];
    if (threadIdx.x < KEXP) s[threadIdx.x] = 0;
    __syncthreads();
    int total = gridDim.x * blockDim.x;
    for (int i = blockIdx.x * blockDim.x + threadIdx.x; i < n; i += total)
        atomicAdd(&s[y[i]], 1);
    __syncthreads();
    if (threadIdx.x < KEXP) atomicAdd(&g_counts[threadIdx.x], s[threadIdx.x]);
}

__global__ void k_scan() {
    int o = 0;
    for (int k = 0; k < KEXP; k++) {
        g_off[k] = o;
        g_cursor[k] = o;
        o += g_counts[k];
    }
    g_off[KEXP] = o;
}

__global__ void k_scatter(const int* __restrict__ y, int n) {
    int lane = threadIdx.x & 31;
    int total = gridDim.x * blockDim.x;
    for (int i = blockIdx.x * blockDim.x + threadIdx.x;; i += total) {
        unsigned amask = __ballot_sync(0xffffffffu, i < n);
        if (amask == 0) break;
        if (i < n) {
            int k = y[i];
            unsigned m = __match_any_sync(amask, k);
            int leader = __ffs(m) - 1;
            int rank = __popc(m & ((1u << lane) - 1u));
            int base = 0;
            if (lane == leader) base = atomicAdd(&g_cursor[k], __popc(m));
            base = __shfl_sync(amask, base, leader);
            g_perm[base + rank] = i;
        }
    }
}

// ---------------- main fused MLP kernel ---------------------------------------
// smem layout (ull units):
//   w1u[1024]  (j<32, c<32):  (W1[j][c], W1[j][c+32])
//   w2u[2048]  (j<64, c<32):  (W2[j][c], W2[j][c+32])
//   w3u[1024]  (j<64, c<16):  (W3[j][c], W3[j][c+16])
//   b1u[32], b2u[32], b3u[16]
//   sb: float[64][256] per-thread activation columns
#define SMEM_ULLS (1024 + 2048 + 1024 + 32 + 32 + 16)
#define SMEM_BYTES (SMEM_ULLS * 8 + 64 * TPB * 4)

__global__ void __launch_bounds__(TPB, 2) k_main(
    const float* __restrict__ x,
    const float* __restrict__ W1, const float* __restrict__ b1,
    const float* __restrict__ W2, const float* __restrict__ b2,
    const float* __restrict__ W3, const float* __restrict__ b3,
    float* __restrict__ out, int n)
{
    // ---- resolve tile: which expert / row-range does this block own? ----
    int off[KEXP + 1];
#pragma unroll
    for (int k = 0; k <= KEXP; k++) off[k] = g_off[k];

    int bid = blockIdx.x;
    int expert = -1, start = 0, len = 0;
    int tb = 0;
#pragma unroll
    for (int k = 0; k < KEXP; k++) {
        int cnt = off[k + 1] - off[k];
        int nt = (cnt + TPB - 1) >> 8;
        if (expert < 0 && bid < tb + nt) {
            expert = k;
            int t = bid - tb;
            start = off[k] + t * TPB;
            len = min(TPB, cnt - t * TPB);
        }
        tb += nt;
    }
    if (expert < 0) return;  // uniform across block

    extern __shared__ __align__(16) unsigned char smraw[];
    ull* w1u = (ull*)smraw;
    ull* w2u = w1u + 1024;
    ull* w3u = w2u + 2048;
    ull* b1u = w3u + 1024;
    ull* b2u = b1u + 32;
    ull* b3u = b2u + 32;
    float* sb = (float*)(b3u + 16);

    const float* W1k = W1 + expert * (32 * 64);
    const float* W2k = W2 + expert * (64 * 64);
    const float* W3k = W3 + expert * (64 * 32);
    const float* b1k = b1 + expert * 64;
    const float* b2k = b2 + expert * 64;
    const float* b3k = b3 + expert * 32;

    int tid = threadIdx.x;

    // ---- stage packed weights ----
    for (int i = tid; i < 1024; i += TPB) {
        int j = i >> 5, c = i & 31;
        w1u[i] = pk2(W1k[j * 64 + c], W1k[j * 64 + c + 32]);
    }
    for (int i = tid; i < 2048; i += TPB) {
        int j = i >> 5, c = i & 31;
        w2u[i] = pk2(W2k[j * 64 + c], W2k[j * 64 + c + 32]);
    }
    for (int i = tid; i < 1024; i += TPB) {
        int j = i >> 4, c = i & 15;
        w3u[i] = pk2(W3k[j * 32 + c], W3k[j * 32 + c + 16]);
    }
    if (tid < 32) {
        b1u[tid] = pk2(b1k[tid], b1k[tid + 32]);
    } else if (tid < 64) {
        int c = tid - 32;
        b2u[c] = pk2(b2k[c], b2k[c + 32]);
    } else if (tid < 80) {
        int c = tid - 64;
        b3u[c] = pk2(b3k[c], b3k[c + 16]);
    }
    __syncthreads();

    if (tid >= len) return;  // no further block-wide syncs below

    int row = g_perm[start + tid];

    // ---- stage this row's x into per-thread smem column ----
    const float4* xp = (const float4*)(x + (long)row * 32);
#pragma unroll
    for (int q = 0; q < 8; q++) {
        float4 v = xp[q];
        sb[(4 * q + 0) * TPB + tid] = v.x;
        sb[(4 * q + 1) * TPB + tid] = v.y;
        sb[(4 * q + 2) * TPB + tid] = v.z;
        sb[(4 * q + 3) * TPB + tid] = v.w;
    }

    ull h[32];

    // ---- layer 1: 32 -> 64, relu ----
#pragma unroll
    for (int c = 0; c < 32; c++) h[c] = b1u[c];
#pragma unroll 4
    for (int j = 0; j < 32; j++) {
        ull a = dup2(sb[j * TPB + tid]);
        const ulonglong2* wp = (const ulonglong2*)(w1u + j * 32);
#pragma unroll
        for (int cc = 0; cc < 16; cc++) {
            ulonglong2 w = wp[cc];
            h[2 * cc] = fma2(a, w.x, h[2 * cc]);
            h[2 * cc + 1] = fma2(a, w.y, h[2 * cc + 1]);
        }
    }
#pragma unroll
    for (int c = 0; c < 32; c++) {
        float2 p = up2(h[c]);
        sb[c * TPB + tid] = fmaxf(p.x, 0.f);
        sb[(c + 32) * TPB + tid] = fmaxf(p.y, 0.f);
    }

    // ---- layer 2: 64 -> 64, relu ----
#pragma unroll
    for (int c = 0; c < 32; c++) h[c] = b2u[c];
#pragma unroll 2
    for (int j = 0; j < 64; j++) {
        ull a = dup2(sb[j * TPB + tid]);
        const ulonglong2* wp = (const ulonglong2*)(w2u + j * 32);
#pragma unroll
        for (int cc = 0; cc < 16; cc++) {
            ulonglong2 w = wp[cc];
            h[2 * cc] = fma2(a, w.x, h[2 * cc]);
            h[2 * cc + 1] = fma2(a, w.y, h[2 * cc + 1]);
        }
    }
#pragma unroll
    for (int c = 0; c < 32; c++) {
        float2 p = up2(h[c]);
        sb[c * TPB + tid] = fmaxf(p.x, 0.f);
        sb[(c + 32) * TPB + tid] = fmaxf(p.y, 0.f);
    }

    // ---- layer 3: 64 -> 32 (pairs are (c, c+16): .x -> mu, .y -> sigma) ----
    ull o[16];
#pragma unroll
    for (int c = 0; c < 16; c++) o[c] = b3u[c];
#pragma unroll 2
    for (int j = 0; j < 64; j++) {
        ull a = dup2(sb[j * TPB + tid]);
        const ulonglong2* wp = (const ulonglong2*)(w3u + j * 16);
#pragma unroll
        for (int cc = 0; cc < 8; cc++) {
            ulonglong2 w = wp[cc];
            o[2 * cc] = fma2(a, w.x, o[2 * cc]);
            o[2 * cc + 1] = fma2(a, w.y, o[2 * cc + 1]);
        }
    }

    // ---- epilogue: mu / softplus(sigma), scattered stores ----
    float mu[16], sg[16];
#pragma unroll
    for (int c = 0; c < 16; c++) {
        float2 p = up2(o[c]);
        mu[c] = p.x;
        float v = p.y;
        sg[c] = fmaxf(v, 0.f) + log1pf(expf(-fabsf(v)));
    }
    float4* mo = (float4*)(out + (long)row * 16);
    float4* so = (float4*)(out + (long)n * 16 + (long)row * 16);
#pragma unroll
    for (int q = 0; q < 4; q++) {
        mo[q] = make_float4(mu[4 * q], mu[4 * q + 1], mu[4 * q + 2], mu[4 * q + 3]);
        so[q] = make_float4(sg[4 * q], sg[4 * q + 1], sg[4 * q + 2], sg[4 * q + 3]);
    }
}

// ---------------- launch ------------------------------------------------------
extern "C" void kernel_launch(void* const* d_in, const int* in_sizes, int n_in,
                              void* d_out, int out_size) {
    const float* x = (const float*)d_in[0];
    const int* y = (const int*)d_in[1];
    const float* W1 = (const float*)d_in[2];
    const float* b1 = (const float*)d_in[3];
    const float* W2 = (const float*)d_in[4];
    const float* b2 = (const float*)d_in[5];
    const float* W3 = (const float*)d_in[6];
    const float* b3 = (const float*)d_in[7];
    float* out = (float*)d_out;
    int n = in_sizes[1];  // y element count == N

    cudaFuncSetAttribute(k_main, cudaFuncAttributeMaxDynamicSharedMemorySize,
                         SMEM_BYTES);

    k_zero<<<1, 32>>>();
    k_hist<<<512, TPB>>>(y, n);
    k_scan<<<1, 1>>>();
    k_scatter<<<512, TPB>>>(y, n);

    int nb = (n + TPB - 1) / TPB + KEXP;
    k_main<<<nb, TPB, SMEM_BYTES>>>(x, W1, b1, W2, b2, W3, b3, out, n);
}

// round 4
// speedup vs baseline: 2.9412x; 2.9412x over previous
#include <cuda_runtime.h>
#include <cuda_bf16.h>
#include <stdint.h>
#include <math.h>

#define KEXP 8
#define NROWS_MAX 1000000
#define NSLICE 37
#define GRID (KEXP * NSLICE)
#define TPB 256
#define ROWS_PER_BLOCK 256   // 8 warps * 32 rows

// ---------------- device scratch ---------------------------------------------
__device__ int g_counts[KEXP];
__device__ int g_off[KEXP + 1];
__device__ int g_cursor[KEXP];
__device__ int g_ticket;
__device__ int g_perm[NROWS_MAX];

// ---------------- helpers -----------------------------------------------------
// pack two f32 -> bf16x2 (lo in low half)
__device__ __forceinline__ uint32_t pk2(float lo, float hi) {
    uint32_t d;
    asm("cvt.rn.bf16x2.f32 %0, %1, %2;" : "=r"(d) : "f"(hi), "f"(lo));
    return d;
}
// hi/lo split of a pair: ph = bf16x2(v0,v1), pl = bf16x2(residuals)
__device__ __forceinline__ void split_pair(float v0, float v1,
                                           uint32_t& ph, uint32_t& pl) {
    ph = pk2(v0, v1);
    float r0 = v0 - __uint_as_float(ph << 16);
    float r1 = v1 - __uint_as_float(ph & 0xffff0000u);
    pl = pk2(r0, r1);
}

__device__ __forceinline__ void mma_bf16(float* C, const uint32_t* a,
                                         uint32_t b0, uint32_t b1) {
    asm volatile(
        "mma.sync.aligned.m16n8k16.row.col.f32.bf16.bf16.f32 "
        "{%0,%1,%2,%3}, {%4,%5,%6,%7}, {%8,%9}, {%0,%1,%2,%3};"
        : "+f"(C[0]), "+f"(C[1]), "+f"(C[2]), "+f"(C[3])
        : "r"(a[0]), "r"(a[1]), "r"(a[2]), "r"(a[3]), "r"(b0), "r"(b1));
}

// ---------------- bucketing ---------------------------------------------------
__global__ void k_hist(const int* __restrict__ y, int n) {
    __shared__ int s[8][KEXP];
    int tid = threadIdx.x, wid = tid >> 5;
    if (tid < 8 * KEXP) ((int*)s)[tid] = 0;
    __syncthreads();
    int total = gridDim.x * blockDim.x;
    for (int i = blockIdx.x * blockDim.x + tid; i < n; i += total)
        atomicAdd(&s[wid][y[i]], 1);
    __syncthreads();
    if (tid < KEXP) {
        int acc = 0;
#pragma unroll
        for (int w = 0; w < 8; w++) acc += s[w][tid];
        atomicAdd(&g_counts[tid], acc);
    }
    __threadfence();
    if (tid == 0) {
        if (atomicAdd(&g_ticket, 1) == (int)gridDim.x - 1) {
            int o = 0;
#pragma unroll
            for (int k = 0; k < KEXP; k++) {
                g_off[k] = o;
                g_cursor[k] = o;
                o += g_counts[k];
                g_counts[k] = 0;   // reset for next graph replay
            }
            g_off[KEXP] = o;
            g_ticket = 0;
        }
    }
}

#define SC_ELEMS 2048
__global__ void k_scatter(const int* __restrict__ y, int n) {
    __shared__ int cache[SC_ELEMS];
    __shared__ int shist[KEXP];
    __shared__ int scur[KEXP];
    int base = blockIdx.x * SC_ELEMS;
    int cnt = n - base;
    if (cnt > SC_ELEMS) cnt = SC_ELEMS;
    if (cnt <= 0) return;
    int tid = threadIdx.x;
    if (tid < KEXP) shist[tid] = 0;
    __syncthreads();
    for (int i = tid; i < cnt; i += blockDim.x) {
        int k = y[base + i];
        cache[i] = k;
        atomicAdd(&shist[k], 1);
    }
    __syncthreads();
    if (tid < KEXP) scur[tid] = atomicAdd(&g_cursor[tid], shist[tid]);
    __syncthreads();
    for (int i = tid; i < cnt; i += blockDim.x) {
        int slot = atomicAdd(&scur[cache[i]], 1);
        g_perm[slot] = base + i;
    }
}

// ---------------- main mma.sync MLP kernel ------------------------------------
// Weights pre-paired for B fragments: wp[k2][PADN] u32, word = (W[2*k2][n], W[2*k2+1][n])
#define PADN 72   // stride 72 words: bank = (8c+g) -> conflict-free

__global__ void __launch_bounds__(TPB)
k_main(const float* __restrict__ x,
       const float* __restrict__ W1, const float* __restrict__ b1,
       const float* __restrict__ W2, const float* __restrict__ b2,
       const float* __restrict__ W3, const float* __restrict__ b3,
       float* __restrict__ out, int n)
{
    __shared__ uint32_t wp1h[16 * PADN], wp1l[16 * PADN];
    __shared__ uint32_t wp2h[32 * PADN], wp2l[32 * PADN];
    __shared__ uint32_t wp3h[32 * PADN], wp3l[32 * PADN];
    __shared__ float biasS[192];   // b1[0:64] b2[64:128] b3[128:160]

    int tid = threadIdx.x;
    int e = blockIdx.x & 7;
    int slice = blockIdx.x >> 3;

    const float* W1k = W1 + e * 2048;   // [32][64]
    const float* W2k = W2 + e * 4096;   // [64][64]
    const float* W3k = W3 + e * 2048;   // [64][32]

    // ---- stage weights as bf16 hi/lo, k-pair packed ----
    for (int i = tid; i < 2048; i += TPB) {           // W1: K=32, N=64
        int k = i >> 6, nn = i & 63;
        float v = W1k[i];
        unsigned short h = __bfloat16_as_ushort(__float2bfloat16_rn(v));
        float hv = __uint_as_float(((uint32_t)h) << 16);
        unsigned short l = __bfloat16_as_ushort(__float2bfloat16_rn(v - hv));
        int idx = ((k >> 1) * PADN + nn) * 2 + (k & 1);
        ((unsigned short*)wp1h)[idx] = h;
        ((unsigned short*)wp1l)[idx] = l;
    }
    for (int i = tid; i < 4096; i += TPB) {           // W2: K=64, N=64
        int k = i >> 6, nn = i & 63;
        float v = W2k[i];
        unsigned short h = __bfloat16_as_ushort(__float2bfloat16_rn(v));
        float hv = __uint_as_float(((uint32_t)h) << 16);
        unsigned short l = __bfloat16_as_ushort(__float2bfloat16_rn(v - hv));
        int idx = ((k >> 1) * PADN + nn) * 2 + (k & 1);
        ((unsigned short*)wp2h)[idx] = h;
        ((unsigned short*)wp2l)[idx] = l;
    }
    for (int i = tid; i < 2048; i += TPB) {           // W3: K=64, N=32
        int k = i >> 5, nn = i & 31;
        float v = W3k[i];
        unsigned short h = __bfloat16_as_ushort(__float2bfloat16_rn(v));
        float hv = __uint_as_float(((uint32_t)h) << 16);
        unsigned short l = __bfloat16_as_ushort(__float2bfloat16_rn(v - hv));
        int idx = ((k >> 1) * PADN + nn) * 2 + (k & 1);
        ((unsigned short*)wp3h)[idx] = h;
        ((unsigned short*)wp3l)[idx] = l;
    }
    if (tid < 64) biasS[tid] = b1[e * 64 + tid];
    else if (tid < 128) biasS[tid] = b2[e * 64 + (tid - 64)];
    else if (tid < 160) biasS[128 + tid - 128] = b3[e * 32 + (tid - 128)];
    __syncthreads();

    int w = tid >> 5;
    int lane = tid & 31;
    int g = lane >> 2;          // groupID (fragment row)
    int c = lane & 3;           // threadID in group (fragment col pair)

    int off0 = g_off[e];
    int cnt = g_off[e + 1] - off0;
    int ntile = (cnt + ROWS_PER_BLOCK - 1) >> 8;

    for (int t = slice; t < ntile; t += NSLICE) {
        int wbase = t * ROWS_PER_BLOCK + w * 32;   // warp's first row in bucket
        if (wbase >= cnt) continue;

        // sub-row index: s = mm*16 + h*8 + g  for (mm,h) in {0,1}x{0,1}
        int rows[4];
        bool valid[4];
#pragma unroll
        for (int mh = 0; mh < 4; mh++) {
            int mm = mh >> 1, hh = mh & 1;
            int gi = wbase + mm * 16 + hh * 8 + g;
            valid[mh] = gi < cnt;
            rows[mh] = g_perm[off0 + (gi < cnt ? gi : cnt - 1)];
        }

        // ---- layer 1 A fragments from x (hi/lo split) ----
        uint32_t a1h[2][2][4], a1l[2][2][4];
#pragma unroll
        for (int mm = 0; mm < 2; mm++) {
#pragma unroll
            for (int hh = 0; hh < 2; hh++) {
                const float* xr = x + (size_t)rows[mm * 2 + hh] * 32;
#pragma unroll
                for (int kk = 0; kk < 2; kk++) {
                    float2 p0 = *(const float2*)(xr + 2 * c + 16 * kk);
                    float2 p1 = *(const float2*)(xr + 2 * c + 8 + 16 * kk);
                    split_pair(p0.x, p0.y, a1h[mm][kk][hh], a1l[mm][kk][hh]);
                    split_pair(p1.x, p1.y, a1h[mm][kk][2 + hh], a1l[mm][kk][2 + hh]);
                }
            }
        }

        // ---- layer 1: [32x32] @ [32x64] ----
        float C1[2][8][4];
#pragma unroll
        for (int mm = 0; mm < 2; mm++)
#pragma unroll
            for (int j = 0; j < 8; j++)
#pragma unroll
                for (int r = 0; r < 4; r++) C1[mm][j][r] = 0.f;
#pragma unroll
        for (int kk = 0; kk < 2; kk++) {
#pragma unroll
            for (int j = 0; j < 8; j++) {
                int bi = (8 * kk + c) * PADN + 8 * j + g;
                uint32_t b0h = wp1h[bi],            b1h_ = wp1h[bi + 4 * PADN];
                uint32_t b0l = wp1l[bi],            b1l_ = wp1l[bi + 4 * PADN];
#pragma unroll
                for (int mm = 0; mm < 2; mm++) {
                    mma_bf16(C1[mm][j], a1h[mm][kk], b0h, b1h_);
                    mma_bf16(C1[mm][j], a1l[mm][kk], b0h, b1h_);
                    mma_bf16(C1[mm][j], a1h[mm][kk], b0l, b1l_);
                }
            }
        }

        // ---- bias + relu + convert C1 -> layer 2 A fragments ----
        uint32_t a2h[2][4][4], a2l[2][4][4];
#pragma unroll
        for (int j = 0; j < 8; j++) {
            float2 bb = *(const float2*)(biasS + 8 * j + 2 * c);
#pragma unroll
            for (int mm = 0; mm < 2; mm++) {
                float v0 = fmaxf(C1[mm][j][0] + bb.x, 0.f);
                float v1 = fmaxf(C1[mm][j][1] + bb.y, 0.f);
                float v2 = fmaxf(C1[mm][j][2] + bb.x, 0.f);
                float v3 = fmaxf(C1[mm][j][3] + bb.y, 0.f);
                int kk = j >> 1, half = j & 1;  // n-tile j -> kfrag j/2, regs {0,1}+2*half
                split_pair(v0, v1, a2h[mm][kk][2 * half],     a2l[mm][kk][2 * half]);
                split_pair(v2, v3, a2h[mm][kk][2 * half + 1], a2l[mm][kk][2 * half + 1]);
            }
        }

        // ---- layer 2: [32x64] @ [64x64] ----
        float C2[2][8][4];
#pragma unroll
        for (int mm = 0; mm < 2; mm++)
#pragma unroll
            for (int j = 0; j < 8; j++)
#pragma unroll
                for (int r = 0; r < 4; r++) C2[mm][j][r] = 0.f;
#pragma unroll
        for (int kk = 0; kk < 4; kk++) {
#pragma unroll
            for (int j = 0; j < 8; j++) {
                int bi = (8 * kk + c) * PADN + 8 * j + g;
                uint32_t b0h = wp2h[bi],            b1h_ = wp2h[bi + 4 * PADN];
                uint32_t b0l = wp2l[bi],            b1l_ = wp2l[bi + 4 * PADN];
#pragma unroll
                for (int mm = 0; mm < 2; mm++) {
                    mma_bf16(C2[mm][j], a2h[mm][kk], b0h, b1h_);
                    mma_bf16(C2[mm][j], a2l[mm][kk], b0h, b1h_);
                    mma_bf16(C2[mm][j], a2h[mm][kk], b0l, b1l_);
                }
            }
        }

        // ---- bias + relu + convert C2 -> layer 3 A fragments ----
        uint32_t a3h[2][4][4], a3l[2][4][4];
#pragma unroll
        for (int j = 0; j < 8; j++) {
            float2 bb = *(const float2*)(biasS + 64 + 8 * j + 2 * c);
#pragma unroll
            for (int mm = 0; mm < 2; mm++) {
                float v0 = fmaxf(C2[mm][j][0] + bb.x, 0.f);
                float v1 = fmaxf(C2[mm][j][1] + bb.y, 0.f);
                float v2 = fmaxf(C2[mm][j][2] + bb.x, 0.f);
                float v3 = fmaxf(C2[mm][j][3] + bb.y, 0.f);
                int kk = j >> 1, half = j & 1;
                split_pair(v0, v1, a3h[mm][kk][2 * half],     a3l[mm][kk][2 * half]);
                split_pair(v2, v3, a3h[mm][kk][2 * half + 1], a3l[mm][kk][2 * half + 1]);
            }
        }

        // ---- layer 3: [32x64] @ [64x32] ----
        float C3[2][4][4];
#pragma unroll
        for (int mm = 0; mm < 2; mm++)
#pragma unroll
            for (int j = 0; j < 4; j++)
#pragma unroll
                for (int r = 0; r < 4; r++) C3[mm][j][r] = 0.f;
#pragma unroll
        for (int kk = 0; kk < 4; kk++) {
#pragma unroll
            for (int j = 0; j < 4; j++) {
                int bi = (8 * kk + c) * PADN + 8 * j + g;
                uint32_t b0h = wp3h[bi],            b1h_ = wp3h[bi + 4 * PADN];
                uint32_t b0l = wp3l[bi],            b1l_ = wp3l[bi + 4 * PADN];
#pragma unroll
                for (int mm = 0; mm < 2; mm++) {
                    mma_bf16(C3[mm][j], a3h[mm][kk], b0h, b1h_);
                    mma_bf16(C3[mm][j], a3l[mm][kk], b0h, b1h_);
                    mma_bf16(C3[mm][j], a3h[mm][kk], b0l, b1l_);
                }
            }
        }

        // ---- epilogue: mu (tiles 0,1), sigma=softplus (tiles 2,3) ----
#pragma unroll
        for (int mm = 0; mm < 2; mm++) {
#pragma unroll
            for (int j = 0; j < 4; j++) {
                float2 bb = *(const float2*)(biasS + 128 + 8 * j + 2 * c);
                float v0 = C3[mm][j][0] + bb.x;
                float v1 = C3[mm][j][1] + bb.y;
                float v2 = C3[mm][j][2] + bb.x;
                float v3 = C3[mm][j][3] + bb.y;
                size_t colbase, rbase0, rbase1;
                if (j < 2) {            // mu
                    colbase = 8 * j + 2 * c;
                } else {                // sigma
                    v0 = fmaxf(v0, 0.f) + log1pf(expf(-fabsf(v0)));
                    v1 = fmaxf(v1, 0.f) + log1pf(expf(-fabsf(v1)));
                    v2 = fmaxf(v2, 0.f) + log1pf(expf(-fabsf(v2)));
                    v3 = fmaxf(v3, 0.f) + log1pf(expf(-fabsf(v3)));
                    colbase = (size_t)n * 16 + 8 * (j - 2) + 2 * c;
                }
                rbase0 = (size_t)rows[mm * 2 + 0] * 16;
                rbase1 = (size_t)rows[mm * 2 + 1] * 16;
                if (valid[mm * 2 + 0])
                    *(float2*)(out + rbase0 + colbase) = make_float2(v0, v1);
                if (valid[mm * 2 + 1])
                    *(float2*)(out + rbase1 + colbase) = make_float2(v2, v3);
            }
        }
    }
}

// ---------------- launch ------------------------------------------------------
extern "C" void kernel_launch(void* const* d_in, const int* in_sizes, int n_in,
                              void* d_out, int out_size) {
    const float* x  = (const float*)d_in[0];
    const int*   y  = (const int*)d_in[1];
    const float* W1 = (const float*)d_in[2];
    const float* b1 = (const float*)d_in[3];
    const float* W2 = (const float*)d_in[4];
    const float* b2 = (const float*)d_in[5];
    const float* W3 = (const float*)d_in[6];
    const float* b3 = (const float*)d_in[7];
    float* out = (float*)d_out;
    int n = in_sizes[1];

    k_hist<<<512, 256>>>(y, n);
    k_scatter<<<(n + SC_ELEMS - 1) / SC_ELEMS, 256>>>(y, n);
    k_main<<<GRID, TPB>>>(x, W1, b1, W2, b2, W3, b3, out, n);
}

// round 5
// speedup vs baseline: 3.5975x; 1.2232x over previous
#include <cuda_runtime.h>
#include <cuda_bf16.h>
#include <stdint.h>
#include <math.h>

#define KEXP 8
#define NROWS_MAX 1000000
#define NSLICE 37
#define GRID (KEXP * NSLICE)
#define TPB 256
#define ROWS_PER_BLOCK 128   // 8 warps * 16 rows

// ---------------- device scratch ---------------------------------------------
__device__ int g_counts[KEXP];
__device__ int g_off[KEXP + 1];
__device__ int g_cursor[KEXP];
__device__ int g_ticket;
__device__ int g_perm[NROWS_MAX];

// ---------------- helpers -----------------------------------------------------
__device__ __forceinline__ uint32_t pk2(float lo, float hi) {
    uint32_t d;
    asm("cvt.rn.bf16x2.f32 %0, %1, %2;" : "=r"(d) : "f"(hi), "f"(lo));
    return d;
}
__device__ __forceinline__ void split_pair(float v0, float v1,
                                           uint32_t& ph, uint32_t& pl) {
    ph = pk2(v0, v1);
    float r0 = v0 - __uint_as_float(ph << 16);
    float r1 = v1 - __uint_as_float(ph & 0xffff0000u);
    pl = pk2(r0, r1);
}

__device__ __forceinline__ void mma_bf16(float* C, const uint32_t* a,
                                         uint32_t b0, uint32_t b1) {
    asm volatile(
        "mma.sync.aligned.m16n8k16.row.col.f32.bf16.bf16.f32 "
        "{%0,%1,%2,%3}, {%4,%5,%6,%7}, {%8,%9}, {%0,%1,%2,%3};"
        : "+f"(C[0]), "+f"(C[1]), "+f"(C[2]), "+f"(C[3])
        : "r"(a[0]), "r"(a[1]), "r"(a[2]), "r"(a[3]), "r"(b0), "r"(b1));
}

__device__ __forceinline__ float softplus_f(float v) {
    return fmaxf(v, 0.f) + __logf(1.f + __expf(-fabsf(v)));
}

// ---------------- bucketing ---------------------------------------------------
__global__ void k_hist(const int* __restrict__ y, int n) {
    __shared__ int s[8][KEXP];
    int tid = threadIdx.x, wid = tid >> 5;
    if (tid < 8 * KEXP) ((int*)s)[tid] = 0;
    __syncthreads();
    int total = gridDim.x * blockDim.x;
    for (int i = blockIdx.x * blockDim.x + tid; i < n; i += total)
        atomicAdd(&s[wid][y[i]], 1);
    __syncthreads();
    if (tid < KEXP) {
        int acc = 0;
#pragma unroll
        for (int w = 0; w < 8; w++) acc += s[w][tid];
        atomicAdd(&g_counts[tid], acc);
    }
    __threadfence();
    if (tid == 0) {
        if (atomicAdd(&g_ticket, 1) == (int)gridDim.x - 1) {
            int o = 0;
#pragma unroll
            for (int k = 0; k < KEXP; k++) {
                g_off[k] = o;
                g_cursor[k] = o;
                o += g_counts[k];
                g_counts[k] = 0;   // reset for next graph replay
            }
            g_off[KEXP] = o;
            g_ticket = 0;
        }
    }
}

#define SC_ELEMS 2048
__global__ void k_scatter(const int* __restrict__ y, int n) {
    __shared__ int cache[SC_ELEMS];
    __shared__ int shist[KEXP];
    __shared__ int scur[KEXP];
    int base = blockIdx.x * SC_ELEMS;
    int cnt = n - base;
    if (cnt > SC_ELEMS) cnt = SC_ELEMS;
    if (cnt <= 0) return;
    int tid = threadIdx.x;
    if (tid < KEXP) shist[tid] = 0;
    __syncthreads();
    for (int i = tid; i < cnt; i += blockDim.x) {
        int k = y[base + i];
        cache[i] = k;
        atomicAdd(&shist[k], 1);
    }
    __syncthreads();
    if (tid < KEXP) scur[tid] = atomicAdd(&g_cursor[tid], shist[tid]);
    __syncthreads();
    for (int i = tid; i < cnt; i += blockDim.x) {
        int slot = atomicAdd(&scur[cache[i]], 1);
        g_perm[slot] = base + i;
    }
}

// ---------------- main mma.sync MLP kernel ------------------------------------
#define PADN 72   // stride 72 words: bank = (8c+g) -> conflict-free

__global__ void __launch_bounds__(TPB, 2)
k_main(const float* __restrict__ x,
       const float* __restrict__ W1, const float* __restrict__ b1,
       const float* __restrict__ W2, const float* __restrict__ b2,
       const float* __restrict__ W3, const float* __restrict__ b3,
       float* __restrict__ out, int n)
{
    __shared__ uint32_t wp1h[16 * PADN], wp1l[16 * PADN];
    __shared__ uint32_t wp2h[32 * PADN], wp2l[32 * PADN];
    __shared__ uint32_t wp3h[32 * PADN], wp3l[32 * PADN];
    __shared__ float biasS[192];   // b1[0:64] b2[64:128] b3[128:160]

    int tid = threadIdx.x;
    int e = blockIdx.x & 7;
    int slice = blockIdx.x >> 3;

    const float* W1k = W1 + e * 2048;   // [32][64]
    const float* W2k = W2 + e * 4096;   // [64][64]
    const float* W3k = W3 + e * 2048;   // [64][32]

    // ---- stage weights as bf16 hi/lo, k-pair packed for B fragments ----
    for (int i = tid; i < 2048; i += TPB) {           // W1: K=32, N=64
        int k = i >> 6, nn = i & 63;
        float v = W1k[i];
        unsigned short h = __bfloat16_as_ushort(__float2bfloat16_rn(v));
        float hv = __uint_as_float(((uint32_t)h) << 16);
        unsigned short l = __bfloat16_as_ushort(__float2bfloat16_rn(v - hv));
        int idx = ((k >> 1) * PADN + nn) * 2 + (k & 1);
        ((unsigned short*)wp1h)[idx] = h;
        ((unsigned short*)wp1l)[idx] = l;
    }
    for (int i = tid; i < 4096; i += TPB) {           // W2: K=64, N=64
        int k = i >> 6, nn = i & 63;
        float v = W2k[i];
        unsigned short h = __bfloat16_as_ushort(__float2bfloat16_rn(v));
        float hv = __uint_as_float(((uint32_t)h) << 16);
        unsigned short l = __bfloat16_as_ushort(__float2bfloat16_rn(v - hv));
        int idx = ((k >> 1) * PADN + nn) * 2 + (k & 1);
        ((unsigned short*)wp2h)[idx] = h;
        ((unsigned short*)wp2l)[idx] = l;
    }
    for (int i = tid; i < 2048; i += TPB) {           // W3: K=64, N=32
        int k = i >> 5, nn = i & 31;
        float v = W3k[i];
        unsigned short h = __bfloat16_as_ushort(__float2bfloat16_rn(v));
        float hv = __uint_as_float(((uint32_t)h) << 16);
        unsigned short l = __bfloat16_as_ushort(__float2bfloat16_rn(v - hv));
        int idx = ((k >> 1) * PADN + nn) * 2 + (k & 1);
        ((unsigned short*)wp3h)[idx] = h;
        ((unsigned short*)wp3l)[idx] = l;
    }
    if (tid < 64) biasS[tid] = b1[e * 64 + tid];
    else if (tid < 128) biasS[tid] = b2[e * 64 + (tid - 64)];
    else if (tid < 160) biasS[128 + tid - 128] = b3[e * 32 + (tid - 128)];
    __syncthreads();

    int w = tid >> 5;
    int lane = tid & 31;
    int g = lane >> 2;          // groupID (fragment row)
    int c = lane & 3;           // threadID in group (fragment col pair)

    int off0 = g_off[e];
    int cnt = g_off[e + 1] - off0;
    int ntile = (cnt + ROWS_PER_BLOCK - 1) >> 7;

    for (int t = slice; t < ntile; t += NSLICE) {
        int wbase = t * ROWS_PER_BLOCK + w * 16;   // warp's first row in bucket
        if (wbase >= cnt) continue;

        int rows[2];
        bool valid[2];
#pragma unroll
        for (int hh = 0; hh < 2; hh++) {
            int gi = wbase + hh * 8 + g;
            valid[hh] = gi < cnt;
            rows[hh] = g_perm[off0 + (gi < cnt ? gi : cnt - 1)];
        }

        // ---- layer 1 A fragments from x (hi/lo split) ----
        uint32_t a1h[2][4], a1l[2][4];
#pragma unroll
        for (int hh = 0; hh < 2; hh++) {
            const float* xr = x + (size_t)rows[hh] * 32;
#pragma unroll
            for (int kk = 0; kk < 2; kk++) {
                float2 p0 = *(const float2*)(xr + 2 * c + 16 * kk);
                float2 p1 = *(const float2*)(xr + 2 * c + 8 + 16 * kk);
                split_pair(p0.x, p0.y, a1h[kk][hh],     a1l[kk][hh]);
                split_pair(p1.x, p1.y, a1h[kk][2 + hh], a1l[kk][2 + hh]);
            }
        }

        // ---- layer 1: [16x32] @ [32x64]  (bias pre-loaded into C) ----
        float C1[8][4];
#pragma unroll
        for (int j = 0; j < 8; j++) {
            float2 bb = *(const float2*)(biasS + 8 * j + 2 * c);
            C1[j][0] = bb.x; C1[j][1] = bb.y; C1[j][2] = bb.x; C1[j][3] = bb.y;
        }
#pragma unroll
        for (int kk = 0; kk < 2; kk++) {
#pragma unroll
            for (int j = 0; j < 8; j++) {
                int bi = (8 * kk + c) * PADN + 8 * j + g;
                uint32_t b0h = wp1h[bi], b1h_ = wp1h[bi + 4 * PADN];
                uint32_t b0l = wp1l[bi], b1l_ = wp1l[bi + 4 * PADN];
                mma_bf16(C1[j], a1h[kk], b0h, b1h_);
                mma_bf16(C1[j], a1l[kk], b0h, b1h_);
                mma_bf16(C1[j], a1h[kk], b0l, b1l_);
            }
        }

        // ---- relu + convert C1 -> layer 2 A fragments ----
        uint32_t a2h[4][4], a2l[4][4];
#pragma unroll
        for (int j = 0; j < 8; j++) {
            float v0 = fmaxf(C1[j][0], 0.f);
            float v1 = fmaxf(C1[j][1], 0.f);
            float v2 = fmaxf(C1[j][2], 0.f);
            float v3 = fmaxf(C1[j][3], 0.f);
            int kk = j >> 1, half = j & 1;
            split_pair(v0, v1, a2h[kk][2 * half],     a2l[kk][2 * half]);
            split_pair(v2, v3, a2h[kk][2 * half + 1], a2l[kk][2 * half + 1]);
        }

        // ---- layer 2: [16x64] @ [64x64] ----
        float C2[8][4];
#pragma unroll
        for (int j = 0; j < 8; j++) {
            float2 bb = *(const float2*)(biasS + 64 + 8 * j + 2 * c);
            C2[j][0] = bb.x; C2[j][1] = bb.y; C2[j][2] = bb.x; C2[j][3] = bb.y;
        }
#pragma unroll
        for (int kk = 0; kk < 4; kk++) {
#pragma unroll
            for (int j = 0; j < 8; j++) {
                int bi = (8 * kk + c) * PADN + 8 * j + g;
                uint32_t b0h = wp2h[bi], b1h_ = wp2h[bi + 4 * PADN];
                uint32_t b0l = wp2l[bi], b1l_ = wp2l[bi + 4 * PADN];
                mma_bf16(C2[j], a2h[kk], b0h, b1h_);
                mma_bf16(C2[j], a2l[kk], b0h, b1h_);
                mma_bf16(C2[j], a2h[kk], b0l, b1l_);
            }
        }

        // ---- relu + convert C2 -> layer 3 A fragments ----
        uint32_t a3h[4][4], a3l[4][4];
#pragma unroll
        for (int j = 0; j < 8; j++) {
            float v0 = fmaxf(C2[j][0], 0.f);
            float v1 = fmaxf(C2[j][1], 0.f);
            float v2 = fmaxf(C2[j][2], 0.f);
            float v3 = fmaxf(C2[j][3], 0.f);
            int kk = j >> 1, half = j & 1;
            split_pair(v0, v1, a3h[kk][2 * half],     a3l[kk][2 * half]);
            split_pair(v2, v3, a3h[kk][2 * half + 1], a3l[kk][2 * half + 1]);
        }

        // ---- layer 3: [16x64] @ [64x32] ----
        float C3[4][4];
#pragma unroll
        for (int j = 0; j < 4; j++) {
            float2 bb = *(const float2*)(biasS + 128 + 8 * j + 2 * c);
            C3[j][0] = bb.x; C3[j][1] = bb.y; C3[j][2] = bb.x; C3[j][3] = bb.y;
        }
#pragma unroll
        for (int kk = 0; kk < 4; kk++) {
#pragma unroll
            for (int j = 0; j < 4; j++) {
                int bi = (8 * kk + c) * PADN + 8 * j + g;
                uint32_t b0h = wp3h[bi], b1h_ = wp3h[bi + 4 * PADN];
                uint32_t b0l = wp3l[bi], b1l_ = wp3l[bi + 4 * PADN];
                mma_bf16(C3[j], a3h[kk], b0h, b1h_);
                mma_bf16(C3[j], a3l[kk], b0h, b1h_);
                mma_bf16(C3[j], a3h[kk], b0l, b1l_);
            }
        }

        // ---- epilogue: mu (tiles 0,1), sigma=softplus (tiles 2,3) ----
#pragma unroll
        for (int j = 0; j < 4; j++) {
            float v0 = C3[j][0], v1 = C3[j][1], v2 = C3[j][2], v3 = C3[j][3];
            size_t colbase;
            if (j < 2) {
                colbase = 8 * j + 2 * c;
            } else {
                v0 = softplus_f(v0); v1 = softplus_f(v1);
                v2 = softplus_f(v2); v3 = softplus_f(v3);
                colbase = (size_t)n * 16 + 8 * (j - 2) + 2 * c;
            }
            if (valid[0])
                *(float2*)(out + (size_t)rows[0] * 16 + colbase) = make_float2(v0, v1);
            if (valid[1])
                *(float2*)(out + (size_t)rows[1] * 16 + colbase) = make_float2(v2, v3);
        }
    }
}

// ---------------- launch ------------------------------------------------------
extern "C" void kernel_launch(void* const* d_in, const int* in_sizes, int n_in,
                              void* d_out, int out_size) {
    const float* x  = (const float*)d_in[0];
    const int*   y  = (const int*)d_in[1];
    const float* W1 = (const float*)d_in[2];
    const float* b1 = (const float*)d_in[3];
    const float* W2 = (const float*)d_in[4];
    const float* b2 = (const float*)d_in[5];
    const float* W3 = (const float*)d_in[6];
    const float* b3 = (const float*)d_in[7];
    float* out = (float*)d_out;
    int n = in_sizes[1];

    k_hist<<<512, 256>>>(y, n);
    k_scatter<<<(n + SC_ELEMS - 1) / SC_ELEMS, 256>>>(y, n);
    k_main<<<GRID, TPB>>>(x, W1, b1, W2, b2, W3, b3, out, n);
}